// round 15
// baseline (speedup 1.0000x reference)
#include <cuda_runtime.h>
#include <cuda_fp16.h>
#include <cstdint>

#define DINL __device__ __forceinline__
#define SCALE_F 0.022097086912079608f  // 1/sqrt(2048)

// ---------- scratch (all fp16) ----------
__device__ __half g_J[640 * 2048];           // joint [b*10+t][e]
__device__ __half g_K[2 * 64 * 1024 * 16];   // keys, SCALE folded, [r][b][d][t16]
__device__ __half g_V[2 * 640 * 1024];       // values [r][row][d]
__device__ __half g_O[2 * 640 * 2048];       // relu(tanh(weighted)) [r*640+row][e]
__device__ __half g_W[9699328];              // converted: [audio|video|Wq|Wv1|Wv2|Wf]
// weights stored k-pair interleaved: u32[r*N+n] = half2(W[2r][n], W[2r+1][n])

#define OW_A   0
#define OW_V   655360
#define OW_WQ  1310720
#define OW_WV1 5505024
#define OW_WV2 6553600
#define OW_WF  7602176

DINL float tanhx(float x) {
    float y; asm("tanh.approx.f32 %0, %1;" : "=f"(y) : "f"(x)); return y;
}
DINL uint32_t tanh2(uint32_t x) {   // packed f16x2 tanh (one MUFU op, two values)
    uint32_t y; asm("tanh.approx.f16x2 %0, %1;" : "=r"(y) : "r"(x)); return y;
}
DINL uint32_t h2u(float lo, float hi) {  // pack two f32 -> f16x2 (lo in low bits)
    uint32_t r; asm("cvt.rn.f16x2.f32 %0, %1, %2;" : "=r"(r) : "f"(hi), "f"(lo));
    return r;
}
DINL uint32_t hh2u(__half lo, __half hi) {
    __half2 h = __halves2half2(lo, hi);
    return *reinterpret_cast<uint32_t*>(&h);
}
DINL void mma16(float* c, uint32_t a0, uint32_t a1, uint32_t a2, uint32_t a3,
                uint32_t b0, uint32_t b1) {
    asm volatile(
        "mma.sync.aligned.m16n8k16.row.col.f32.f16.f16.f32 "
        "{%0,%1,%2,%3},{%4,%5,%6,%7},{%8,%9},{%0,%1,%2,%3};"
        : "+f"(c[0]), "+f"(c[1]), "+f"(c[2]), "+f"(c[3])
        : "r"(a0), "r"(a1), "r"(a2), "r"(a3), "r"(b0), "r"(b1));
}
DINL void cpa16(uint32_t dst, const void* src) {
    asm volatile("cp.async.cg.shared.global [%0], [%1], 16;\n" :: "r"(dst), "l"(src));
}
DINL void cpa_commit() { asm volatile("cp.async.commit_group;\n" ::: "memory"); }
template<int W> DINL void cpa_wait() {
    asm volatile("cp.async.wait_group %0;\n" :: "n"(W) : "memory");
}

// ---------- convert inputs + weights to fp16 (weights: k-pair interleaved) ----------
__global__ __launch_bounds__(256) void k_round(
    const float* __restrict__ a, const float* __restrict__ v,
    const float* __restrict__ wq, const float* __restrict__ wv1,
    const float* __restrict__ wv2, const float* __restrict__ wf)
{
    int i = blockIdx.x * 256 + threadIdx.x;     // 16B output chunk (8 halves)
    uint4 o;
    if (i < 163840) {                            // activations, natural layout
        const float4* src = (i < 81920) ? (const float4*)a : (const float4*)v;
        int b4 = (i < 81920) ? 0 : 81920;
        float4 x0 = src[(size_t)(i - b4) * 2], x1 = src[(size_t)(i - b4) * 2 + 1];
        o.x = h2u(x0.x, x0.y); o.y = h2u(x0.z, x0.w);
        o.z = h2u(x1.x, x1.y); o.w = h2u(x1.z, x1.w);
    } else {                                     // weights, interleaved k-pairs
        const float* W; int N, cb;
        if      (i < 688128) { W = wq;  N = 2048; cb = 163840; }
        else if (i < 819200) { W = wv1; N = 1024; cb = 688128; }
        else if (i < 950272) { W = wv2; N = 1024; cb = 819200; }
        else                 { W = wf;  N = 1024; cb = 950272; }
        int u = (i - cb) * 4;
        int r = u / N, n = u - r * N;
        float4 w0 = *(const float4*)(W + (size_t)(2 * r) * N + n);
        float4 w1 = *(const float4*)(W + (size_t)(2 * r + 1) * N + n);
        o.x = h2u(w0.x, w1.x); o.y = h2u(w0.y, w1.y);
        o.z = h2u(w0.z, w1.z); o.w = h2u(w0.w, w1.w);
    }
    ((uint4*)g_W)[i] = o;
}

// ---------- key linears ----------
__global__ __launch_bounds__(256) void k_key(
    const float* __restrict__ audio, const float* __restrict__ video,
    const float* __restrict__ Wk1, const float* __restrict__ bk1,
    const float* __restrict__ Wk2, const float* __restrict__ bk2)
{
    int b = blockIdx.x, r = blockIdx.y;
    const float* X  = r ? video : audio;
    const float* Wk = r ? Wk2 : Wk1;
    const float* bk = r ? bk2 : bk1;
    __shared__ float sW[100], sb[10];
    if (threadIdx.x < 100) sW[threadIdx.x] = Wk[threadIdx.x];
    if (threadIdx.x < 10)  sb[threadIdx.x] = bk[threadIdx.x];
    __syncthreads();
    const float* xb = X + (size_t)b * 10240;
    __half* kout = g_K + (size_t)(r * 64 + b) * 16384;
    for (int d = threadIdx.x; d < 1024; d += 256) {
        float a[10];
        #pragma unroll
        for (int t = 0; t < 10; ++t) a[t] = xb[t * 1024 + d];
        __half* krow = kout + (size_t)d * 16;
        #pragma unroll
        for (int t = 10; t < 16; ++t) krow[t] = __float2half(0.0f);
        #pragma unroll
        for (int t = 0; t < 10; ++t) {
            float s = sb[t];
            #pragma unroll
            for (int tp = 0; tp < 10; ++tp) s += a[tp] * sW[tp * 10 + t];
            krow[t] = __float2half_rn(s * SCALE_F);
        }
    }
}

// ---------- fp16 GEMM: BM=32 BN=64 BK=32, 3-stage cp.async ----------
// stage bytes: A[32][40]h = 2560, B[16][72]u32 = 4608 -> 7168/stage
__global__ __launch_bounds__(256) void k_gemm_tc(
    const __half* A0, const __half* A1, const __half* A0z, const __half* A1z,
    int Asplit, int lda,
    const uint32_t* W0, const uint32_t* W1,
    const float* bias0, const float* bias1,
    int cSel, size_t cStride, int N, int K)
{
    extern __shared__ float smg[];
    char* smb = (char*)smg;
    uint32_t sb32 = (uint32_t)__cvta_generic_to_shared(smg);
    int z = blockIdx.z;
    const __half* Ap0 = z ? A0z : A0;
    const __half* Ap1 = z ? A1z : A1;
    const uint32_t* W  = z ? W1 : W0;
    const float* bias  = z ? bias1 : bias0;
    __half* C = (cSel == 0 ? g_J : g_V) + (size_t)z * cStride;

    int tid = threadIdx.x, lane = tid & 31, warp = tid >> 5;
    int g = lane >> 2, j = lane & 3;
    int wm = (warp >> 2) * 16, wn = (warp & 3) * 16;
    int row0 = blockIdx.y * 32, col0 = blockIdx.x * 64;
    float acc[2][4] = {};
    int nt = K >> 5;

    #define GEMM_ISSUE(TI, ST) do {                                             \
        int kb_ = (TI) << 5;                                                    \
        uint32_t sA_ = sb32 + (uint32_t)(ST) * 7168u;                           \
        uint32_t sB_ = sA_ + 2560u;                                             \
        if (tid < 128) {                                                        \
            int ar_ = tid >> 2, g4_ = tid & 3;                                  \
            int gk_ = kb_ + g4_ * 8;                                            \
            const __half* ap_ = (gk_ < Asplit)                                  \
                ? (Ap0 + (size_t)(row0 + ar_) * lda + gk_)                      \
                : (Ap1 + (size_t)(row0 + ar_) * lda + (gk_ - Asplit));          \
            cpa16(sA_ + (uint32_t)(ar_ * 80 + g4_ * 16), ap_);                  \
        }                                                                       \
        { int br_ = tid >> 4, g4_ = tid & 15;                                   \
          cpa16(sB_ + (uint32_t)(br_ * 288 + g4_ * 16),                         \
                W + (size_t)((TI) * 16 + br_) * N + col0 + g4_ * 4); }          \
    } while (0)

    if (0 < nt) { GEMM_ISSUE(0, 0); } cpa_commit();
    if (1 < nt) { GEMM_ISSUE(1, 1); } cpa_commit();

    for (int ti = 0; ti < nt; ++ti) {
        cpa_wait<1>();
        __syncthreads();
        int tin = ti + 2;
        if (tin < nt) { GEMM_ISSUE(tin, tin % 3); }
        cpa_commit();

        const uint32_t* Asu = (const uint32_t*)(smb + (ti % 3) * 7168);
        const uint32_t* Bsu = (const uint32_t*)(smb + (ti % 3) * 7168 + 2560);
        #pragma unroll
        for (int s = 0; s < 2; ++s) {
            int rr = wm + g;
            uint32_t a0 = Asu[rr * 20 + s * 8 + j];
            uint32_t a1 = Asu[(rr + 8) * 20 + s * 8 + j];
            uint32_t a2 = Asu[rr * 20 + s * 8 + 4 + j];
            uint32_t a3 = Asu[(rr + 8) * 20 + s * 8 + 4 + j];
            #pragma unroll
            for (int ni = 0; ni < 2; ++ni) {
                int nn = wn + ni * 8 + g;
                uint32_t b0 = Bsu[(s * 8 + j) * 72 + nn];
                uint32_t b1 = Bsu[(s * 8 + 4 + j) * 72 + nn];
                mma16(acc[ni], a0, a1, a2, a3, b0, b1);
            }
        }
    }
    #undef GEMM_ISSUE

    #pragma unroll
    for (int ni = 0; ni < 2; ++ni) {
        int rr = row0 + wm + g;
        int cc = col0 + wn + ni * 8 + 2 * j;
        float b0v = bias[cc], b1v = bias[cc + 1];
        *(uint32_t*)(C + (size_t)rr * N + cc) = h2u(acc[ni][0] + b0v, acc[ni][1] + b1v);
        *(uint32_t*)(C + (size_t)(rr + 8) * N + cc) = h2u(acc[ni][2] + b0v, acc[ni][3] + b1v);
    }
}

// ---------- fused fc_fusion (both branches) + residual -> d_out ----------
// BM=32 BN=32 BK=32. stage: A0[32][40]h=2560, A1=2560, B[16][36]u32=2304 -> 7424
__global__ __launch_bounds__(256) void k_fuse(
    const float* __restrict__ audio, const float* __restrict__ video,
    const uint32_t* __restrict__ Wfu, const float* __restrict__ bfb,
    float* __restrict__ out)
{
    extern __shared__ float smg[];
    char* smb = (char*)smg;
    uint32_t sb32 = (uint32_t)__cvta_generic_to_shared(smg);
    int tid = threadIdx.x, lane = tid & 31, warp = tid >> 5;
    int g = lane >> 2, j = lane & 3;
    int wm = (warp >> 2) * 16, wn = (warp & 3) * 8;
    int row0 = blockIdx.y * 32, col0 = blockIdx.x * 32;
    float acc[2][4] = {};   // [branch][4]
    const int nt = 64;      // K = 2048

    #define FU_ISSUE(TI, ST) do {                                               \
        int kb_ = (TI) << 5;                                                    \
        uint32_t sA0_ = sb32 + (uint32_t)(ST) * 7424u;                          \
        uint32_t sB_  = sA0_ + 5120u;                                           \
        if (tid < 128) {                                                        \
            int r_ = tid >> 2, g4_ = tid & 3;                                   \
            cpa16(sA0_ + (uint32_t)(r_ * 80 + g4_ * 16),                        \
                  g_O + (size_t)(row0 + r_) * 2048 + kb_ + g4_ * 8);            \
            int br_ = tid >> 3, g8_ = tid & 7;                                  \
            cpa16(sB_ + (uint32_t)(br_ * 144 + g8_ * 16),                       \
                  Wfu + (size_t)((TI) * 16 + br_) * 1024 + col0 + g8_ * 4);     \
        } else {                                                                \
            int t2 = tid - 128, r_ = t2 >> 2, g4_ = t2 & 3;                     \
            cpa16(sA0_ + 2560u + (uint32_t)(r_ * 80 + g4_ * 16),                \
                  g_O + (size_t)(640 + row0 + r_) * 2048 + kb_ + g4_ * 8);      \
        }                                                                       \
    } while (0)

    FU_ISSUE(0, 0); cpa_commit();
    FU_ISSUE(1, 1); cpa_commit();

    for (int ti = 0; ti < nt; ++ti) {
        cpa_wait<1>();
        __syncthreads();
        int tin = ti + 2;
        if (tin < nt) { FU_ISSUE(tin, tin % 3); }
        cpa_commit();

        const uint32_t* A0u = (const uint32_t*)(smb + (ti % 3) * 7424);
        const uint32_t* A1u = A0u + 640;
        const uint32_t* Bsu = (const uint32_t*)(smb + (ti % 3) * 7424 + 5120);
        #pragma unroll
        for (int s = 0; s < 2; ++s) {
            int rr = wm + g;
            uint32_t a0[4], a1[4];
            a0[0] = A0u[rr * 20 + s * 8 + j];       a0[1] = A0u[(rr + 8) * 20 + s * 8 + j];
            a0[2] = A0u[rr * 20 + s * 8 + 4 + j];   a0[3] = A0u[(rr + 8) * 20 + s * 8 + 4 + j];
            a1[0] = A1u[rr * 20 + s * 8 + j];       a1[1] = A1u[(rr + 8) * 20 + s * 8 + j];
            a1[2] = A1u[rr * 20 + s * 8 + 4 + j];   a1[3] = A1u[(rr + 8) * 20 + s * 8 + 4 + j];
            int nn = wn + g;
            uint32_t b0 = Bsu[(s * 8 + j) * 36 + nn];
            uint32_t b1 = Bsu[(s * 8 + 4 + j) * 36 + nn];
            mma16(acc[0], a0[0], a0[1], a0[2], a0[3], b0, b1);
            mma16(acc[1], a1[0], a1[1], a1[2], a1[3], b0, b1);
        }
    }
    #undef FU_ISSUE

    {
        int rr = row0 + wm + g, cc = col0 + wn + 2 * j;
        float b0 = bfb[cc], b1 = bfb[cc + 1];
        size_t o0 = (size_t)rr * 1024 + cc, o1 = (size_t)(rr + 8) * 1024 + cc;
        float v0 = fmaxf(acc[0][0] + b0, 0.f) + fmaxf(acc[1][0] + b0, 0.f)
                 + audio[o0] + video[o0];
        float v1 = fmaxf(acc[0][1] + b1, 0.f) + fmaxf(acc[1][1] + b1, 0.f)
                 + audio[o0 + 1] + video[o0 + 1];
        float v2 = fmaxf(acc[0][2] + b0, 0.f) + fmaxf(acc[1][2] + b0, 0.f)
                 + audio[o1] + video[o1];
        float v3 = fmaxf(acc[0][3] + b1, 0.f) + fmaxf(acc[1][3] + b1, 0.f)
                 + audio[o1 + 1] + video[o1 + 1];
        *(float2*)(out + o0) = make_float2(v0, v1);
        *(float2*)(out + o1) = make_float2(v2, v3);
    }
}

// ---------- fused co-attention branch, fp16: 2 e-tiles/warp, 3-stage ----------
// stage bytes: K[64][24]h = 3072, V[16][72]h = 2304 -> 5376/stage
__global__ __launch_bounds__(256, 2) void k_branch_tc()
{
    __shared__ char smb[3 * 5376];
    uint32_t sb32 = (uint32_t)__cvta_generic_to_shared(smb);

    int eblk = blockIdx.x, b = blockIdx.y, r = blockIdx.z;
    int tid = threadIdx.x, lane = tid & 31, warp = tid >> 5;
    int g = lane >> 2, j = lane & 3;

    const __half* gk  = g_K + (size_t)(r * 64 + b) * 16384;
    const __half* gvb = g_V + (size_t)r * 655360 + (size_t)b * 10240;

    // J fragments (A of GEMM1, k=t covers all 16 padded t in ONE mma)
    uint32_t jf[2][4];
    {
        const __half* jb = g_J + (size_t)b * 20480;
        #pragma unroll
        for (int tile = 0; tile < 2; ++tile) {
            int eT = eblk * 256 + warp * 32 + tile * 16 + g;
            jf[tile][0] = hh2u(jb[(size_t)(2 * j) * 2048 + eT],
                               jb[(size_t)(2 * j + 1) * 2048 + eT]);
            jf[tile][1] = hh2u(jb[(size_t)(2 * j) * 2048 + eT + 8],
                               jb[(size_t)(2 * j + 1) * 2048 + eT + 8]);
            if (j == 0) {
                jf[tile][2] = hh2u(jb[(size_t)8 * 2048 + eT], jb[(size_t)9 * 2048 + eT]);
                jf[tile][3] = hh2u(jb[(size_t)8 * 2048 + eT + 8], jb[(size_t)9 * 2048 + eT + 8]);
            } else { jf[tile][2] = 0u; jf[tile][3] = 0u; }
        }
    }

    // zero V pad rows (t=10..15) in all 3 stages
    for (int i = tid; i < 3 * 6 * 36; i += 256) {
        int st = i / 216, rem = i - st * 216;
        int row = 10 + rem / 36, col = rem % 36;
        ((uint32_t*)(smb + st * 5376 + 3072))[row * 36 + col] = 0u;
    }

    #define BR_ISSUE(CH, ST) do {                                               \
        uint32_t base_ = sb32 + (uint32_t)(ST) * 5376u;                         \
        if (tid < 128) {                                                        \
            int d_ = tid >> 1, g4_ = tid & 1;                                   \
            cpa16(base_ + (uint32_t)(d_ * 48 + g4_ * 16),                       \
                  gk + (size_t)((CH) * 64 + d_) * 16 + g4_ * 8);                \
        } else if (tid < 208) {                                                 \
            int v_ = tid - 128, t_ = v_ >> 3, gi_ = v_ & 7;                     \
            cpa16(base_ + 3072u + (uint32_t)(t_ * 144 + gi_ * 16),              \
                  gvb + (size_t)t_ * 1024 + (CH) * 64 + gi_ * 8);               \
        }                                                                       \
    } while (0)

    BR_ISSUE(0, 0); cpa_commit();
    BR_ISSUE(1, 1); cpa_commit();

    float accW[2][2][4] = {};

    for (int ch = 0; ch < 16; ++ch) {
        cpa_wait<1>();
        __syncthreads();
        if (ch + 2 < 16) { BR_ISSUE(ch + 2, (ch + 2) % 3); }
        cpa_commit();

        const uint32_t* Ku = (const uint32_t*)(smb + (ch % 3) * 5376);        // stride 12
        const uint32_t* Vu = (const uint32_t*)(smb + (ch % 3) * 5376 + 3072); // stride 36

        #pragma unroll
        for (int dh = 0; dh < 2; ++dh) {
            float accS[2][4][4] = {};
            // GEMM1: S^T[e,d] += J^T K^T over k=t(16), one mma per (e-tile, d8)
            #pragma unroll
            for (int ni = 0; ni < 4; ++ni) {
                int dd = dh * 32 + ni * 8 + g;
                uint32_t b0 = Ku[dd * 12 + j];
                uint32_t b1 = Ku[dd * 12 + 4 + j];
                mma16(accS[0][ni], jf[0][0], jf[0][1], jf[0][2], jf[0][3], b0, b1);
                mma16(accS[1][ni], jf[1][0], jf[1][1], jf[1][2], jf[1][3], b0, b1);
            }
            // cvt-pack -> packed f16x2 tanh (half the MUFU ops) -> A fragments
            #pragma unroll
            for (int q = 0; q < 2; ++q) {
                uint32_t aa[2][4];
                #pragma unroll
                for (int et = 0; et < 2; ++et) {
                    aa[et][0] = tanh2(h2u(accS[et][2 * q][0],     accS[et][2 * q][1]));
                    aa[et][1] = tanh2(h2u(accS[et][2 * q][2],     accS[et][2 * q][3]));
                    aa[et][2] = tanh2(h2u(accS[et][2 * q + 1][0], accS[et][2 * q + 1][1]));
                    aa[et][3] = tanh2(h2u(accS[et][2 * q + 1][2], accS[et][2 * q + 1][3]));
                }
                #pragma unroll
                for (int nt = 0; nt < 2; ++nt) {
                    int tt = nt * 8 + g;
                    uint32_t b0 = Vu[tt * 36 + dh * 16 + q * 8 + j];
                    uint32_t b1 = Vu[tt * 36 + dh * 16 + q * 8 + 4 + j];
                    mma16(accW[0][nt], aa[0][0], aa[0][1], aa[0][2], aa[0][3], b0, b1);
                    mma16(accW[1][nt], aa[1][0], aa[1][1], aa[1][2], aa[1][3], b0, b1);
                }
            }
        }
    }
    #undef BR_ISSUE

    // epilogue: g_O[t][e] = fp16(relu(tanh(accW)))  (f32 tanh — only 2.6M values)
    #pragma unroll
    for (int et = 0; et < 2; ++et) {
        int e = eblk * 256 + warp * 32 + et * 16 + g;
        #pragma unroll
        for (int nt = 0; nt < 2; ++nt) {
            int t0 = nt * 8 + 2 * j;
            if (t0 < 10) {
                size_t base = ((size_t)r * 640 + b * 10 + t0) * 2048;
                g_O[base + e]     = __float2half_rn(fmaxf(tanhx(accW[et][nt][0]), 0.0f));
                g_O[base + e + 8] = __float2half_rn(fmaxf(tanhx(accW[et][nt][2]), 0.0f));
            }
            if (t0 + 1 < 10) {
                size_t base = ((size_t)r * 640 + b * 10 + t0 + 1) * 2048;
                g_O[base + e]     = __float2half_rn(fmaxf(tanhx(accW[et][nt][1]), 0.0f));
                g_O[base + e + 8] = __float2half_rn(fmaxf(tanhx(accW[et][nt][3]), 0.0f));
            }
        }
    }
}

extern "C" void kernel_launch(void* const* d_in, const int* in_sizes, int n_in,
                              void* d_out, int out_size)
{
    const float* audio = (const float*)d_in[0];
    const float* video = (const float*)d_in[1];
    const float* Wq  = (const float*)d_in[2];
    const float* bq  = (const float*)d_in[3];
    const float* Wk1 = (const float*)d_in[4];
    const float* bk1 = (const float*)d_in[5];
    const float* Wk2 = (const float*)d_in[6];
    const float* bk2 = (const float*)d_in[7];
    const float* Wv1 = (const float*)d_in[8];
    const float* bv1 = (const float*)d_in[9];
    const float* Wv2 = (const float*)d_in[10];
    const float* bv2 = (const float*)d_in[11];
    const float* Wf  = (const float*)d_in[12];
    const float* bf  = (const float*)d_in[13];
    float* out = (float*)d_out;

    static __half* wb = nullptr;
    static cudaStream_t s1 = nullptr, s2 = nullptr;
    static cudaEvent_t eS, eR, eK, eV;
    if (!wb) {
        cudaGetSymbolAddress((void**)&wb, g_W);
        cudaStreamCreateWithFlags(&s1, cudaStreamNonBlocking);
        cudaStreamCreateWithFlags(&s2, cudaStreamNonBlocking);
        cudaEventCreateWithFlags(&eS, cudaEventDisableTiming);
        cudaEventCreateWithFlags(&eR, cudaEventDisableTiming);
        cudaEventCreateWithFlags(&eK, cudaEventDisableTiming);
        cudaEventCreateWithFlags(&eV, cudaEventDisableTiming);
    }
    const __half* hA = wb + OW_A;
    const __half* hV = wb + OW_V;
    const uint32_t* Wqu  = (const uint32_t*)(wb + OW_WQ);
    const uint32_t* Wv1u = (const uint32_t*)(wb + OW_WV1);
    const uint32_t* Wv2u = (const uint32_t*)(wb + OW_WV2);
    const uint32_t* Wfu  = (const uint32_t*)(wb + OW_WF);

    // fork: key linears on s2 (raw fp32 inputs)
    cudaEventRecord(eS, 0);
    cudaStreamWaitEvent(s2, eS, 0);
    k_key<<<dim3(64, 2), 256, 0, s2>>>(audio, video, Wk1, bk1, Wk2, bk2);
    cudaEventRecord(eK, s2);

    // fp16 conversion (activations natural, weights k-pair interleaved)
    k_round<<<4736, 256>>>(audio, video, Wq, Wv1, Wv2, Wf);
    cudaEventRecord(eR, 0);

    // val1/val2 on s1 (z), concurrent with joint
    cudaStreamWaitEvent(s1, eR, 0);
    k_gemm_tc<<<dim3(16, 20, 2), 256, 21504, s1>>>(
        hA, hA, hV, hV, 1024, 1024, Wv1u, Wv2u, bv1, bv2,
        1, (size_t)640 * 1024, 1024, 1024);
    cudaEventRecord(eV, s1);

    // joint = concat(audio,video) @ Wq + bq -> g_J
    k_gemm_tc<<<dim3(32, 20), 256, 21504>>>(
        hA, hV, hA, hV, 1024, 1024, Wqu, Wqu, bq, bq,
        0, 0, 2048, 2048);

    // join, then branch
    cudaStreamWaitEvent(0, eV, 0);
    cudaStreamWaitEvent(0, eK, 0);
    k_branch_tc<<<dim3(8, 64, 2), 256>>>();

    // fused fc_fusion (both branches) + residual -> d_out
    k_fuse<<<dim3(32, 20), 256, 22272>>>(audio, video, Wfu, bf, out);
}

// round 16
// speedup vs baseline: 1.1087x; 1.1087x over previous
#include <cuda_runtime.h>
#include <cuda_fp16.h>
#include <cstdint>

#define DINL __device__ __forceinline__
#define SCALE_F 0.022097086912079608f  // 1/sqrt(2048)

// ---------- scratch (all fp16) ----------
__device__ __half g_J[640 * 2048];           // joint [b*10+t][e]
__device__ __half g_K[2 * 64 * 1024 * 16];   // keys, SCALE folded, [r][b][d][t16]
__device__ __half g_V[2 * 640 * 1024];       // values [r][row][d]
__device__ __half g_O[2 * 640 * 2048];       // relu(tanh(weighted)) [r*640+row][e]
__device__ __half g_W[9699328];              // converted: [audio|video|Wq|Wv1|Wv2|Wf]
// weights stored k-pair interleaved: u32[r*N+n] = half2(W[2r][n], W[2r+1][n])

#define OW_A   0
#define OW_V   655360
#define OW_WQ  1310720
#define OW_WV1 5505024
#define OW_WV2 6553600
#define OW_WF  7602176

DINL float tanhx(float x) {
    float y; asm("tanh.approx.f32 %0, %1;" : "=f"(y) : "f"(x)); return y;
}
DINL uint32_t tanh2(uint32_t x) {   // packed f16x2 tanh (one MUFU op, two values)
    uint32_t y; asm("tanh.approx.f16x2 %0, %1;" : "=r"(y) : "r"(x)); return y;
}
DINL uint32_t h2u(float lo, float hi) {  // pack two f32 -> f16x2 (lo in low bits)
    uint32_t r; asm("cvt.rn.f16x2.f32 %0, %1, %2;" : "=r"(r) : "f"(hi), "f"(lo));
    return r;
}
DINL uint32_t hh2u(__half lo, __half hi) {
    __half2 h = __halves2half2(lo, hi);
    return *reinterpret_cast<uint32_t*>(&h);
}
DINL void mma16(float* c, uint32_t a0, uint32_t a1, uint32_t a2, uint32_t a3,
                uint32_t b0, uint32_t b1) {
    asm volatile(
        "mma.sync.aligned.m16n8k16.row.col.f32.f16.f16.f32 "
        "{%0,%1,%2,%3},{%4,%5,%6,%7},{%8,%9},{%0,%1,%2,%3};"
        : "+f"(c[0]), "+f"(c[1]), "+f"(c[2]), "+f"(c[3])
        : "r"(a0), "r"(a1), "r"(a2), "r"(a3), "r"(b0), "r"(b1));
}
DINL void cpa16(uint32_t dst, const void* src) {
    asm volatile("cp.async.cg.shared.global [%0], [%1], 16;\n" :: "r"(dst), "l"(src));
}
DINL void cpa_commit() { asm volatile("cp.async.commit_group;\n" ::: "memory"); }
template<int W> DINL void cpa_wait() {
    asm volatile("cp.async.wait_group %0;\n" :: "n"(W) : "memory");
}

// ---------- convert inputs + weights to fp16 (weights: k-pair interleaved) ----------
__global__ __launch_bounds__(256) void k_round(
    const float* __restrict__ a, const float* __restrict__ v,
    const float* __restrict__ wq, const float* __restrict__ wv1,
    const float* __restrict__ wv2, const float* __restrict__ wf)
{
    int i = blockIdx.x * 256 + threadIdx.x;     // 16B output chunk (8 halves)
    uint4 o;
    if (i < 163840) {                            // activations, natural layout
        const float4* src = (i < 81920) ? (const float4*)a : (const float4*)v;
        int b4 = (i < 81920) ? 0 : 81920;
        float4 x0 = src[(size_t)(i - b4) * 2], x1 = src[(size_t)(i - b4) * 2 + 1];
        o.x = h2u(x0.x, x0.y); o.y = h2u(x0.z, x0.w);
        o.z = h2u(x1.x, x1.y); o.w = h2u(x1.z, x1.w);
    } else {                                     // weights, interleaved k-pairs
        const float* W; int N, cb;
        if      (i < 688128) { W = wq;  N = 2048; cb = 163840; }
        else if (i < 819200) { W = wv1; N = 1024; cb = 688128; }
        else if (i < 950272) { W = wv2; N = 1024; cb = 819200; }
        else                 { W = wf;  N = 1024; cb = 950272; }
        int u = (i - cb) * 4;
        int r = u / N, n = u - r * N;
        float4 w0 = *(const float4*)(W + (size_t)(2 * r) * N + n);
        float4 w1 = *(const float4*)(W + (size_t)(2 * r + 1) * N + n);
        o.x = h2u(w0.x, w1.x); o.y = h2u(w0.y, w1.y);
        o.z = h2u(w0.z, w1.z); o.w = h2u(w0.w, w1.w);
    }
    ((uint4*)g_W)[i] = o;
}

// ---------- key linears ----------
__global__ __launch_bounds__(256) void k_key(
    const float* __restrict__ audio, const float* __restrict__ video,
    const float* __restrict__ Wk1, const float* __restrict__ bk1,
    const float* __restrict__ Wk2, const float* __restrict__ bk2)
{
    int b = blockIdx.x, r = blockIdx.y;
    const float* X  = r ? video : audio;
    const float* Wk = r ? Wk2 : Wk1;
    const float* bk = r ? bk2 : bk1;
    __shared__ float sW[100], sb[10];
    if (threadIdx.x < 100) sW[threadIdx.x] = Wk[threadIdx.x];
    if (threadIdx.x < 10)  sb[threadIdx.x] = bk[threadIdx.x];
    __syncthreads();
    const float* xb = X + (size_t)b * 10240;
    __half* kout = g_K + (size_t)(r * 64 + b) * 16384;
    for (int d = threadIdx.x; d < 1024; d += 256) {
        float a[10];
        #pragma unroll
        for (int t = 0; t < 10; ++t) a[t] = xb[t * 1024 + d];
        __half* krow = kout + (size_t)d * 16;
        #pragma unroll
        for (int t = 10; t < 16; ++t) krow[t] = __float2half(0.0f);
        #pragma unroll
        for (int t = 0; t < 10; ++t) {
            float s = sb[t];
            #pragma unroll
            for (int tp = 0; tp < 10; ++tp) s += a[tp] * sW[tp * 10 + t];
            krow[t] = __float2half_rn(s * SCALE_F);
        }
    }
}

// ---------- fp16 GEMM: BM=64 BN=64 BK=32, 3-stage cp.async ----------
// stage bytes: A[64][40]h = 5120, B[16][72]u32 = 4608 -> 9728/stage
__global__ __launch_bounds__(256) void k_gemm_tc(
    const __half* A0, const __half* A1, const __half* A0z, const __half* A1z,
    int Asplit, int lda,
    const uint32_t* W0, const uint32_t* W1,
    const float* bias0, const float* bias1,
    int cSel, size_t cStride, int N, int K)
{
    extern __shared__ float smg[];
    char* smb = (char*)smg;
    uint32_t sb32 = (uint32_t)__cvta_generic_to_shared(smg);
    int z = blockIdx.z;
    const __half* Ap0 = z ? A0z : A0;
    const __half* Ap1 = z ? A1z : A1;
    const uint32_t* W  = z ? W1 : W0;
    const float* bias  = z ? bias1 : bias0;
    __half* C = (cSel == 0 ? g_J : g_V) + (size_t)z * cStride;

    int tid = threadIdx.x, lane = tid & 31, warp = tid >> 5;
    int g = lane >> 2, j = lane & 3;
    int wm = (warp >> 2) * 32, wn = (warp & 3) * 16;
    int row0 = blockIdx.y * 64, col0 = blockIdx.x * 64;
    float acc[2][2][4] = {};
    int nt = K >> 5;

    #define GEMM_ISSUE(TI, ST) do {                                             \
        int kb_ = (TI) << 5;                                                    \
        uint32_t sA_ = sb32 + (uint32_t)(ST) * 9728u;                           \
        uint32_t sB_ = sA_ + 5120u;                                             \
        { int ar_ = tid >> 2, g4_ = tid & 3;                                    \
          int gk_ = kb_ + g4_ * 8;                                              \
          const __half* ap_ = (gk_ < Asplit)                                    \
              ? (Ap0 + (size_t)(row0 + ar_) * lda + gk_)                        \
              : (Ap1 + (size_t)(row0 + ar_) * lda + (gk_ - Asplit));            \
          cpa16(sA_ + (uint32_t)(ar_ * 80 + g4_ * 16), ap_); }                  \
        { int br_ = tid >> 4, g4_ = tid & 15;                                   \
          cpa16(sB_ + (uint32_t)(br_ * 288 + g4_ * 16),                         \
                W + (size_t)((TI) * 16 + br_) * N + col0 + g4_ * 4); }          \
    } while (0)

    if (0 < nt) { GEMM_ISSUE(0, 0); } cpa_commit();
    if (1 < nt) { GEMM_ISSUE(1, 1); } cpa_commit();

    for (int ti = 0; ti < nt; ++ti) {
        cpa_wait<1>();
        __syncthreads();
        int tin = ti + 2;
        if (tin < nt) { GEMM_ISSUE(tin, tin % 3); }
        cpa_commit();

        const uint32_t* Asu = (const uint32_t*)(smb + (ti % 3) * 9728);
        const uint32_t* Bsu = (const uint32_t*)(smb + (ti % 3) * 9728 + 5120);
        #pragma unroll
        for (int s = 0; s < 2; ++s) {
            uint32_t a[2][4];
            #pragma unroll
            for (int mi = 0; mi < 2; ++mi) {
                int rr = wm + mi * 16 + g;
                a[mi][0] = Asu[rr * 20 + s * 8 + j];
                a[mi][1] = Asu[(rr + 8) * 20 + s * 8 + j];
                a[mi][2] = Asu[rr * 20 + s * 8 + 4 + j];
                a[mi][3] = Asu[(rr + 8) * 20 + s * 8 + 4 + j];
            }
            #pragma unroll
            for (int ni = 0; ni < 2; ++ni) {
                int nn = wn + ni * 8 + g;
                uint32_t b0 = Bsu[(s * 8 + j) * 72 + nn];
                uint32_t b1 = Bsu[(s * 8 + 4 + j) * 72 + nn];
                mma16(acc[0][ni], a[0][0], a[0][1], a[0][2], a[0][3], b0, b1);
                mma16(acc[1][ni], a[1][0], a[1][1], a[1][2], a[1][3], b0, b1);
            }
        }
    }
    #undef GEMM_ISSUE

    #pragma unroll
    for (int mi = 0; mi < 2; ++mi)
        #pragma unroll
        for (int ni = 0; ni < 2; ++ni) {
            int rr = row0 + wm + mi * 16 + g;
            int cc = col0 + wn + ni * 8 + 2 * j;
            float b0v = bias[cc], b1v = bias[cc + 1];
            float v0 = acc[mi][ni][0] + b0v, v1 = acc[mi][ni][1] + b1v;
            float v2 = acc[mi][ni][2] + b0v, v3 = acc[mi][ni][3] + b1v;
            *(uint32_t*)(C + (size_t)rr * N + cc) = h2u(v0, v1);
            *(uint32_t*)(C + (size_t)(rr + 8) * N + cc) = h2u(v2, v3);
        }
}

// ---------- fused fc_fusion (both branches) + residual -> d_out ----------
// stage: A0[32][40]h=2560, A1=2560, B[16][72]u32=4608 -> 9728/stage
__global__ __launch_bounds__(256) void k_fuse(
    const float* __restrict__ audio, const float* __restrict__ video,
    const uint32_t* __restrict__ Wfu, const float* __restrict__ bfb,
    float* __restrict__ out)
{
    extern __shared__ float smg[];
    char* smb = (char*)smg;
    uint32_t sb32 = (uint32_t)__cvta_generic_to_shared(smg);
    int tid = threadIdx.x, lane = tid & 31, warp = tid >> 5;
    int g = lane >> 2, j = lane & 3;
    int wm = (warp >> 2) * 16, wn = (warp & 3) * 16;
    int row0 = blockIdx.y * 32, col0 = blockIdx.x * 64;
    float acc[2][2][4] = {};
    const int nt = 64;   // K = 2048

    #define FU_ISSUE(TI, ST) do {                                               \
        int kb_ = (TI) << 5;                                                    \
        uint32_t sA0_ = sb32 + (uint32_t)(ST) * 9728u;                          \
        uint32_t sB_  = sA0_ + 5120u;                                           \
        if (tid < 128) {                                                        \
            int r_ = tid >> 2, g4_ = tid & 3;                                   \
            cpa16(sA0_ + (uint32_t)(r_ * 80 + g4_ * 16),                        \
                  g_O + (size_t)(row0 + r_) * 2048 + kb_ + g4_ * 8);            \
        } else {                                                                \
            int t2 = tid - 128, r_ = t2 >> 2, g4_ = t2 & 3;                     \
            cpa16(sA0_ + 2560u + (uint32_t)(r_ * 80 + g4_ * 16),                \
                  g_O + (size_t)(640 + row0 + r_) * 2048 + kb_ + g4_ * 8);      \
        }                                                                       \
        { int br_ = tid >> 4, g4_ = tid & 15;                                   \
          cpa16(sB_ + (uint32_t)(br_ * 288 + g4_ * 16),                         \
                Wfu + (size_t)((TI) * 16 + br_) * 1024 + col0 + g4_ * 4); }     \
    } while (0)

    FU_ISSUE(0, 0); cpa_commit();
    FU_ISSUE(1, 1); cpa_commit();

    for (int ti = 0; ti < nt; ++ti) {
        cpa_wait<1>();
        __syncthreads();
        int tin = ti + 2;
        if (tin < nt) { FU_ISSUE(tin, tin % 3); }
        cpa_commit();

        const uint32_t* A0u = (const uint32_t*)(smb + (ti % 3) * 9728);
        const uint32_t* A1u = A0u + 640;
        const uint32_t* Bsu = (const uint32_t*)(smb + (ti % 3) * 9728 + 5120);
        #pragma unroll
        for (int s = 0; s < 2; ++s) {
            int rr = wm + g;
            uint32_t a0[4], a1[4];
            a0[0] = A0u[rr * 20 + s * 8 + j];       a0[1] = A0u[(rr + 8) * 20 + s * 8 + j];
            a0[2] = A0u[rr * 20 + s * 8 + 4 + j];   a0[3] = A0u[(rr + 8) * 20 + s * 8 + 4 + j];
            a1[0] = A1u[rr * 20 + s * 8 + j];       a1[1] = A1u[(rr + 8) * 20 + s * 8 + j];
            a1[2] = A1u[rr * 20 + s * 8 + 4 + j];   a1[3] = A1u[(rr + 8) * 20 + s * 8 + 4 + j];
            #pragma unroll
            for (int ni = 0; ni < 2; ++ni) {
                int nn = wn + ni * 8 + g;
                uint32_t b0 = Bsu[(s * 8 + j) * 72 + nn];
                uint32_t b1 = Bsu[(s * 8 + 4 + j) * 72 + nn];
                mma16(acc[0][ni], a0[0], a0[1], a0[2], a0[3], b0, b1);
                mma16(acc[1][ni], a1[0], a1[1], a1[2], a1[3], b0, b1);
            }
        }
    }
    #undef FU_ISSUE

    #pragma unroll
    for (int ni = 0; ni < 2; ++ni) {
        int rr = row0 + wm + g, cc = col0 + wn + ni * 8 + 2 * j;
        float b0 = bfb[cc], b1 = bfb[cc + 1];
        size_t o0 = (size_t)rr * 1024 + cc, o1 = (size_t)(rr + 8) * 1024 + cc;
        float v0 = fmaxf(acc[0][ni][0] + b0, 0.f) + fmaxf(acc[1][ni][0] + b0, 0.f)
                 + audio[o0] + video[o0];
        float v1 = fmaxf(acc[0][ni][1] + b1, 0.f) + fmaxf(acc[1][ni][1] + b1, 0.f)
                 + audio[o0 + 1] + video[o0 + 1];
        float v2 = fmaxf(acc[0][ni][2] + b0, 0.f) + fmaxf(acc[1][ni][2] + b0, 0.f)
                 + audio[o1] + video[o1];
        float v3 = fmaxf(acc[0][ni][3] + b1, 0.f) + fmaxf(acc[1][ni][3] + b1, 0.f)
                 + audio[o1 + 1] + video[o1 + 1];
        *(float2*)(out + o0) = make_float2(v0, v1);
        *(float2*)(out + o1) = make_float2(v2, v3);
    }
}

// ---------- fused co-attention branch, fp16: 2 e-tiles/warp, 3-stage ----------
// stage bytes: K[64][24]h = 3072, V[16][72]h = 2304 -> 5376/stage
__global__ __launch_bounds__(256, 2) void k_branch_tc()
{
    __shared__ char smb[3 * 5376];
    uint32_t sb32 = (uint32_t)__cvta_generic_to_shared(smb);

    int eblk = blockIdx.x, b = blockIdx.y, r = blockIdx.z;
    int tid = threadIdx.x, lane = tid & 31, warp = tid >> 5;
    int g = lane >> 2, j = lane & 3;

    const __half* gk  = g_K + (size_t)(r * 64 + b) * 16384;
    const __half* gvb = g_V + (size_t)r * 655360 + (size_t)b * 10240;

    // J fragments (A of GEMM1, k=t covers all 16 padded t in ONE mma)
    uint32_t jf[2][4];
    {
        const __half* jb = g_J + (size_t)b * 20480;
        #pragma unroll
        for (int tile = 0; tile < 2; ++tile) {
            int eT = eblk * 256 + warp * 32 + tile * 16 + g;
            jf[tile][0] = hh2u(jb[(size_t)(2 * j) * 2048 + eT],
                               jb[(size_t)(2 * j + 1) * 2048 + eT]);
            jf[tile][1] = hh2u(jb[(size_t)(2 * j) * 2048 + eT + 8],
                               jb[(size_t)(2 * j + 1) * 2048 + eT + 8]);
            if (j == 0) {
                jf[tile][2] = hh2u(jb[(size_t)8 * 2048 + eT], jb[(size_t)9 * 2048 + eT]);
                jf[tile][3] = hh2u(jb[(size_t)8 * 2048 + eT + 8], jb[(size_t)9 * 2048 + eT + 8]);
            } else { jf[tile][2] = 0u; jf[tile][3] = 0u; }
        }
    }

    // zero V pad rows (t=10..15) in all 3 stages
    for (int i = tid; i < 3 * 6 * 36; i += 256) {
        int st = i / 216, rem = i - st * 216;
        int row = 10 + rem / 36, col = rem % 36;
        ((uint32_t*)(smb + st * 5376 + 3072))[row * 36 + col] = 0u;
    }

    #define BR_ISSUE(CH, ST) do {                                               \
        uint32_t base_ = sb32 + (uint32_t)(ST) * 5376u;                         \
        if (tid < 128) {                                                        \
            int d_ = tid >> 1, g4_ = tid & 1;                                   \
            cpa16(base_ + (uint32_t)(d_ * 48 + g4_ * 16),                       \
                  gk + (size_t)((CH) * 64 + d_) * 16 + g4_ * 8);                \
        } else if (tid < 208) {                                                 \
            int v_ = tid - 128, t_ = v_ >> 3, gi_ = v_ & 7;                     \
            cpa16(base_ + 3072u + (uint32_t)(t_ * 144 + gi_ * 16),              \
                  gvb + (size_t)t_ * 1024 + (CH) * 64 + gi_ * 8);               \
        }                                                                       \
    } while (0)

    BR_ISSUE(0, 0); cpa_commit();
    BR_ISSUE(1, 1); cpa_commit();

    float accW[2][2][4] = {};

    for (int ch = 0; ch < 16; ++ch) {
        cpa_wait<1>();
        __syncthreads();
        if (ch + 2 < 16) { BR_ISSUE(ch + 2, (ch + 2) % 3); }
        cpa_commit();

        const uint32_t* Ku = (const uint32_t*)(smb + (ch % 3) * 5376);        // stride 12
        const uint32_t* Vu = (const uint32_t*)(smb + (ch % 3) * 5376 + 3072); // stride 36

        #pragma unroll
        for (int dh = 0; dh < 2; ++dh) {
            float accS[2][4][4] = {};
            // GEMM1: S^T[e,d] += J^T K^T over k=t(16), one mma per (e-tile, d8)
            #pragma unroll
            for (int ni = 0; ni < 4; ++ni) {
                int dd = dh * 32 + ni * 8 + g;
                uint32_t b0 = Ku[dd * 12 + j];
                uint32_t b1 = Ku[dd * 12 + 4 + j];
                mma16(accS[0][ni], jf[0][0], jf[0][1], jf[0][2], jf[0][3], b0, b1);
                mma16(accS[1][ni], jf[1][0], jf[1][1], jf[1][2], jf[1][3], b0, b1);
            }
            // cvt-pack -> packed f16x2 tanh (half the MUFU ops) -> A fragments
            #pragma unroll
            for (int q = 0; q < 2; ++q) {
                uint32_t aa[2][4];
                #pragma unroll
                for (int et = 0; et < 2; ++et) {
                    aa[et][0] = tanh2(h2u(accS[et][2 * q][0],     accS[et][2 * q][1]));
                    aa[et][1] = tanh2(h2u(accS[et][2 * q][2],     accS[et][2 * q][3]));
                    aa[et][2] = tanh2(h2u(accS[et][2 * q + 1][0], accS[et][2 * q + 1][1]));
                    aa[et][3] = tanh2(h2u(accS[et][2 * q + 1][2], accS[et][2 * q + 1][3]));
                }
                #pragma unroll
                for (int nt = 0; nt < 2; ++nt) {
                    int tt = nt * 8 + g;
                    uint32_t b0 = Vu[tt * 36 + dh * 16 + q * 8 + j];
                    uint32_t b1 = Vu[tt * 36 + dh * 16 + q * 8 + 4 + j];
                    mma16(accW[0][nt], aa[0][0], aa[0][1], aa[0][2], aa[0][3], b0, b1);
                    mma16(accW[1][nt], aa[1][0], aa[1][1], aa[1][2], aa[1][3], b0, b1);
                }
            }
        }
    }
    #undef BR_ISSUE

    // epilogue: g_O[t][e] = fp16(relu(tanh(accW)))  (f32 tanh — only 2.6M values)
    #pragma unroll
    for (int et = 0; et < 2; ++et) {
        int e = eblk * 256 + warp * 32 + et * 16 + g;
        #pragma unroll
        for (int nt = 0; nt < 2; ++nt) {
            int t0 = nt * 8 + 2 * j;
            if (t0 < 10) {
                size_t base = ((size_t)r * 640 + b * 10 + t0) * 2048;
                g_O[base + e]     = __float2half_rn(fmaxf(tanhx(accW[et][nt][0]), 0.0f));
                g_O[base + e + 8] = __float2half_rn(fmaxf(tanhx(accW[et][nt][2]), 0.0f));
            }
            if (t0 + 1 < 10) {
                size_t base = ((size_t)r * 640 + b * 10 + t0 + 1) * 2048;
                g_O[base + e]     = __float2half_rn(fmaxf(tanhx(accW[et][nt][1]), 0.0f));
                g_O[base + e + 8] = __float2half_rn(fmaxf(tanhx(accW[et][nt][3]), 0.0f));
            }
        }
    }
}

extern "C" void kernel_launch(void* const* d_in, const int* in_sizes, int n_in,
                              void* d_out, int out_size)
{
    const float* audio = (const float*)d_in[0];
    const float* video = (const float*)d_in[1];
    const float* Wq  = (const float*)d_in[2];
    const float* bq  = (const float*)d_in[3];
    const float* Wk1 = (const float*)d_in[4];
    const float* bk1 = (const float*)d_in[5];
    const float* Wk2 = (const float*)d_in[6];
    const float* bk2 = (const float*)d_in[7];
    const float* Wv1 = (const float*)d_in[8];
    const float* bv1 = (const float*)d_in[9];
    const float* Wv2 = (const float*)d_in[10];
    const float* bv2 = (const float*)d_in[11];
    const float* Wf  = (const float*)d_in[12];
    const float* bf  = (const float*)d_in[13];
    float* out = (float*)d_out;

    static __half* wb = nullptr;
    static cudaStream_t s1 = nullptr, s2 = nullptr;
    static cudaEvent_t eS, eR, eK, eV;
    if (!wb) {
        cudaGetSymbolAddress((void**)&wb, g_W);
        cudaStreamCreateWithFlags(&s1, cudaStreamNonBlocking);
        cudaStreamCreateWithFlags(&s2, cudaStreamNonBlocking);
        cudaEventCreateWithFlags(&eS, cudaEventDisableTiming);
        cudaEventCreateWithFlags(&eR, cudaEventDisableTiming);
        cudaEventCreateWithFlags(&eK, cudaEventDisableTiming);
        cudaEventCreateWithFlags(&eV, cudaEventDisableTiming);
    }
    const __half* hA = wb + OW_A;
    const __half* hV = wb + OW_V;
    const uint32_t* Wqu  = (const uint32_t*)(wb + OW_WQ);
    const uint32_t* Wv1u = (const uint32_t*)(wb + OW_WV1);
    const uint32_t* Wv2u = (const uint32_t*)(wb + OW_WV2);
    const uint32_t* Wfu  = (const uint32_t*)(wb + OW_WF);

    // fork: key linears on s2 (raw fp32 inputs)
    cudaEventRecord(eS, 0);
    cudaStreamWaitEvent(s2, eS, 0);
    k_key<<<dim3(64, 2), 256, 0, s2>>>(audio, video, Wk1, bk1, Wk2, bk2);
    cudaEventRecord(eK, s2);

    // fp16 conversion (activations natural, weights k-pair interleaved)
    k_round<<<4736, 256>>>(audio, video, Wq, Wv1, Wv2, Wf);
    cudaEventRecord(eR, 0);

    // val1/val2 on s1 (z), concurrent with joint
    cudaStreamWaitEvent(s1, eR, 0);
    k_gemm_tc<<<dim3(16, 10, 2), 256, 29184, s1>>>(
        hA, hA, hV, hV, 1024, 1024, Wv1u, Wv2u, bv1, bv2,
        1, (size_t)640 * 1024, 1024, 1024);
    cudaEventRecord(eV, s1);

    // joint = concat(audio,video) @ Wq + bq -> g_J
    k_gemm_tc<<<dim3(32, 10), 256, 29184>>>(
        hA, hV, hA, hV, 1024, 1024, Wqu, Wqu, bq, bq,
        0, 0, 2048, 2048);

    // join, then branch
    cudaStreamWaitEvent(0, eV, 0);
    cudaStreamWaitEvent(0, eK, 0);
    k_branch_tc<<<dim3(8, 64, 2), 256>>>();

    // fused fc_fusion (both branches) + residual -> d_out
    k_fuse<<<dim3(16, 20), 256, 29184>>>(audio, video, Wfu, bf, out);
}

// round 17
// speedup vs baseline: 1.1609x; 1.0471x over previous
#include <cuda_runtime.h>
#include <cuda_fp16.h>
#include <cstdint>

#define DINL __device__ __forceinline__
#define SCALE_F 0.022097086912079608f  // 1/sqrt(2048)

// ---------- scratch ----------
__device__ __half g_J[640 * 2048];           // joint fp16 [b*10+t][e]
__device__ __half g_K[2 * 64 * 1024 * 16];   // keys, SCALE folded, [r][b][d][t16]
__device__ __half g_V[2 * 640 * 1024];       // values [r][row][d]
__device__ __half g_O[2 * 640 * 2048];       // relu(tanh(weighted)) [r*640+row][e]
__device__ __half g_W[9699328];              // fp16: [audio|video|Wq|Wv1|Wv2|Wf]
__device__ float  g_JF[2 * 640 * 2048];      // joint split-K f32 partials [khalf]
__device__ float  g_FF[4 * 640 * 1024];      // fuse split-K f32 partials [khalf*2+branch]
// weights stored k-pair interleaved: u32[r*N+n] = half2(W[2r][n], W[2r+1][n])

#define OW_A   0
#define OW_V   655360
#define OW_WQ  1310720
#define OW_WV1 5505024
#define OW_WV2 6553600
#define OW_WF  7602176

DINL float tanhx(float x) {
    float y; asm("tanh.approx.f32 %0, %1;" : "=f"(y) : "f"(x)); return y;
}
DINL uint32_t tanh2(uint32_t x) {
    uint32_t y; asm("tanh.approx.f16x2 %0, %1;" : "=r"(y) : "r"(x)); return y;
}
DINL uint32_t h2u(float lo, float hi) {  // pack two f32 -> f16x2 (lo in low bits)
    uint32_t r; asm("cvt.rn.f16x2.f32 %0, %1, %2;" : "=r"(r) : "f"(hi), "f"(lo));
    return r;
}
DINL uint32_t hh2u(__half lo, __half hi) {
    __half2 h = __halves2half2(lo, hi);
    return *reinterpret_cast<uint32_t*>(&h);
}
DINL void mma16(float* c, uint32_t a0, uint32_t a1, uint32_t a2, uint32_t a3,
                uint32_t b0, uint32_t b1) {
    asm volatile(
        "mma.sync.aligned.m16n8k16.row.col.f32.f16.f16.f32 "
        "{%0,%1,%2,%3},{%4,%5,%6,%7},{%8,%9},{%0,%1,%2,%3};"
        : "+f"(c[0]), "+f"(c[1]), "+f"(c[2]), "+f"(c[3])
        : "r"(a0), "r"(a1), "r"(a2), "r"(a3), "r"(b0), "r"(b1));
}
DINL void cpa16(uint32_t dst, const void* src) {
    asm volatile("cp.async.cg.shared.global [%0], [%1], 16;\n" :: "r"(dst), "l"(src));
}
DINL void cpa_commit() { asm volatile("cp.async.commit_group;\n" ::: "memory"); }
template<int W> DINL void cpa_wait() {
    asm volatile("cp.async.wait_group %0;\n" :: "n"(W) : "memory");
}

// ---------- convert inputs + weights to fp16 (weights: k-pair interleaved) ----------
__global__ __launch_bounds__(256) void k_round(
    const float* __restrict__ a, const float* __restrict__ v,
    const float* __restrict__ wq, const float* __restrict__ wv1,
    const float* __restrict__ wv2, const float* __restrict__ wf)
{
    int i = blockIdx.x * 256 + threadIdx.x;     // 16B output chunk (8 halves)
    uint4 o;
    if (i < 163840) {                            // activations, natural layout
        const float4* src = (i < 81920) ? (const float4*)a : (const float4*)v;
        int b4 = (i < 81920) ? 0 : 81920;
        float4 x0 = src[(size_t)(i - b4) * 2], x1 = src[(size_t)(i - b4) * 2 + 1];
        o.x = h2u(x0.x, x0.y); o.y = h2u(x0.z, x0.w);
        o.z = h2u(x1.x, x1.y); o.w = h2u(x1.z, x1.w);
    } else {                                     // weights, interleaved k-pairs
        const float* W; int N, cb;
        if      (i < 688128) { W = wq;  N = 2048; cb = 163840; }
        else if (i < 819200) { W = wv1; N = 1024; cb = 688128; }
        else if (i < 950272) { W = wv2; N = 1024; cb = 819200; }
        else                 { W = wf;  N = 1024; cb = 950272; }
        int u = (i - cb) * 4;
        int r = u / N, n = u - r * N;
        float4 w0 = *(const float4*)(W + (size_t)(2 * r) * N + n);
        float4 w1 = *(const float4*)(W + (size_t)(2 * r + 1) * N + n);
        o.x = h2u(w0.x, w1.x); o.y = h2u(w0.y, w1.y);
        o.z = h2u(w0.z, w1.z); o.w = h2u(w0.w, w1.w);
    }
    ((uint4*)g_W)[i] = o;
}

// ---------- key linears ----------
__global__ __launch_bounds__(256) void k_key(
    const float* __restrict__ audio, const float* __restrict__ video,
    const float* __restrict__ Wk1, const float* __restrict__ bk1,
    const float* __restrict__ Wk2, const float* __restrict__ bk2)
{
    int b = blockIdx.x, r = blockIdx.y;
    const float* X  = r ? video : audio;
    const float* Wk = r ? Wk2 : Wk1;
    const float* bk = r ? bk2 : bk1;
    __shared__ float sW[100], sb[10];
    if (threadIdx.x < 100) sW[threadIdx.x] = Wk[threadIdx.x];
    if (threadIdx.x < 10)  sb[threadIdx.x] = bk[threadIdx.x];
    __syncthreads();
    const float* xb = X + (size_t)b * 10240;
    __half* kout = g_K + (size_t)(r * 64 + b) * 16384;
    for (int d = threadIdx.x; d < 1024; d += 256) {
        float a[10];
        #pragma unroll
        for (int t = 0; t < 10; ++t) a[t] = xb[t * 1024 + d];
        __half* krow = kout + (size_t)d * 16;
        #pragma unroll
        for (int t = 10; t < 16; ++t) krow[t] = __float2half(0.0f);
        #pragma unroll
        for (int t = 0; t < 10; ++t) {
            float s = sb[t];
            #pragma unroll
            for (int tp = 0; tp < 10; ++tp) s += a[tp] * sW[tp * 10 + t];
            krow[t] = __float2half_rn(s * SCALE_F);
        }
    }
}

// ---------- fp16 GEMM: BM=64 BN=64 BK=32, 3-stage cp.async ----------
// outMode 0: fp16 out + bias (val). outMode 1: f32 partial, no bias (joint split).
// stage bytes: A[64][40]h = 5120, B[16][72]u32 = 4608 -> 9728/stage
__global__ __launch_bounds__(256) void k_gemm_tc(
    const __half* A0, const __half* A1, const __half* A0z, const __half* A1z,
    int Asplit, int lda,
    const uint32_t* W0, const uint32_t* W1,
    const float* bias0, const float* bias1,
    int cSel, size_t cStride, int N, int K, int outMode)
{
    extern __shared__ float smg[];
    char* smb = (char*)smg;
    uint32_t sb32 = (uint32_t)__cvta_generic_to_shared(smg);
    int z = blockIdx.z;
    const __half* Ap0 = z ? A0z : A0;
    const __half* Ap1 = z ? A1z : A1;
    const uint32_t* W  = z ? W1 : W0;
    const float* bias  = z ? bias1 : bias0;

    int tid = threadIdx.x, lane = tid & 31, warp = tid >> 5;
    int g = lane >> 2, j = lane & 3;
    int wm = (warp >> 2) * 32, wn = (warp & 3) * 16;
    int row0 = blockIdx.y * 64, col0 = blockIdx.x * 64;
    float acc[2][2][4] = {};
    int nt = K >> 5;

    #define GEMM_ISSUE(TI, ST) do {                                             \
        int kb_ = (TI) << 5;                                                    \
        uint32_t sA_ = sb32 + (uint32_t)(ST) * 9728u;                           \
        uint32_t sB_ = sA_ + 5120u;                                             \
        { int ar_ = tid >> 2, g4_ = tid & 3;                                    \
          int gk_ = kb_ + g4_ * 8;                                              \
          const __half* ap_ = (gk_ < Asplit)                                    \
              ? (Ap0 + (size_t)(row0 + ar_) * lda + gk_)                        \
              : (Ap1 + (size_t)(row0 + ar_) * lda + (gk_ - Asplit));            \
          cpa16(sA_ + (uint32_t)(ar_ * 80 + g4_ * 16), ap_); }                  \
        { int br_ = tid >> 4, g4_ = tid & 15;                                   \
          cpa16(sB_ + (uint32_t)(br_ * 288 + g4_ * 16),                         \
                W + (size_t)((TI) * 16 + br_) * N + col0 + g4_ * 4); }          \
    } while (0)

    if (0 < nt) { GEMM_ISSUE(0, 0); } cpa_commit();
    if (1 < nt) { GEMM_ISSUE(1, 1); } cpa_commit();

    for (int ti = 0; ti < nt; ++ti) {
        cpa_wait<1>();
        __syncthreads();
        int tin = ti + 2;
        if (tin < nt) { GEMM_ISSUE(tin, tin % 3); }
        cpa_commit();

        const uint32_t* Asu = (const uint32_t*)(smb + (ti % 3) * 9728);
        const uint32_t* Bsu = (const uint32_t*)(smb + (ti % 3) * 9728 + 5120);
        #pragma unroll
        for (int s = 0; s < 2; ++s) {
            uint32_t a[2][4];
            #pragma unroll
            for (int mi = 0; mi < 2; ++mi) {
                int rr = wm + mi * 16 + g;
                a[mi][0] = Asu[rr * 20 + s * 8 + j];
                a[mi][1] = Asu[(rr + 8) * 20 + s * 8 + j];
                a[mi][2] = Asu[rr * 20 + s * 8 + 4 + j];
                a[mi][3] = Asu[(rr + 8) * 20 + s * 8 + 4 + j];
            }
            #pragma unroll
            for (int ni = 0; ni < 2; ++ni) {
                int nn = wn + ni * 8 + g;
                uint32_t b0 = Bsu[(s * 8 + j) * 72 + nn];
                uint32_t b1 = Bsu[(s * 8 + 4 + j) * 72 + nn];
                mma16(acc[0][ni], a[0][0], a[0][1], a[0][2], a[0][3], b0, b1);
                mma16(acc[1][ni], a[1][0], a[1][1], a[1][2], a[1][3], b0, b1);
            }
        }
    }
    #undef GEMM_ISSUE

    if (outMode == 0) {
        __half* C = g_V + (size_t)z * cStride;
        (void)cSel;
        #pragma unroll
        for (int mi = 0; mi < 2; ++mi)
            #pragma unroll
            for (int ni = 0; ni < 2; ++ni) {
                int rr = row0 + wm + mi * 16 + g;
                int cc = col0 + wn + ni * 8 + 2 * j;
                float b0v = bias[cc], b1v = bias[cc + 1];
                *(uint32_t*)(C + (size_t)rr * N + cc) =
                    h2u(acc[mi][ni][0] + b0v, acc[mi][ni][1] + b1v);
                *(uint32_t*)(C + (size_t)(rr + 8) * N + cc) =
                    h2u(acc[mi][ni][2] + b0v, acc[mi][ni][3] + b1v);
            }
    } else {
        float* Cf = g_JF + (size_t)z * cStride;
        #pragma unroll
        for (int mi = 0; mi < 2; ++mi)
            #pragma unroll
            for (int ni = 0; ni < 2; ++ni) {
                int rr = row0 + wm + mi * 16 + g;
                int cc = col0 + wn + ni * 8 + 2 * j;
                *(float2*)(Cf + (size_t)rr * N + cc) = make_float2(acc[mi][ni][0], acc[mi][ni][1]);
                *(float2*)(Cf + (size_t)(rr + 8) * N + cc) = make_float2(acc[mi][ni][2], acc[mi][ni][3]);
            }
    }
}

// ---------- merge joint halves: g_J = fp16(JF0 + JF1 + bq) ----------
__global__ __launch_bounds__(256) void k_jmerge(const float* __restrict__ bq)
{
    int i = blockIdx.x * 256 + threadIdx.x;   // float4 index over 327680
    float4 p0 = ((const float4*)g_JF)[i];
    float4 p1 = ((const float4*)(g_JF + 1310720))[i];
    int cc = (i * 4) & 2047;
    float4 b = *(const float4*)(bq + cc);
    uint2 o;
    o.x = h2u(p0.x + p1.x + b.x, p0.y + p1.y + b.y);
    o.y = h2u(p0.z + p1.z + b.z, p0.w + p1.w + b.w);
    ((uint2*)g_J)[i] = o;
}

// ---------- fused fc_fusion split-K (both branches) -> f32 partials ----------
// z = khalf. stage: A0[32][40]h=2560, A1=2560, B[16][72]u32=4608 -> 9728/stage
__global__ __launch_bounds__(256) void k_fuse(const uint32_t* __restrict__ Wfu)
{
    extern __shared__ float smg[];
    char* smb = (char*)smg;
    uint32_t sb32 = (uint32_t)__cvta_generic_to_shared(smg);
    int z = blockIdx.z;
    int tid = threadIdx.x, lane = tid & 31, warp = tid >> 5;
    int g = lane >> 2, j = lane & 3;
    int wm = (warp >> 2) * 16, wn = (warp & 3) * 16;
    int row0 = blockIdx.y * 32, col0 = blockIdx.x * 64;
    float acc[2][2][4] = {};
    const int nt = 32;   // K = 1024 per half
    const uint32_t* Wz = Wfu + (size_t)(z * 512) * 1024;
    int ecol0 = z * 1024;

    #define FU_ISSUE(TI, ST) do {                                               \
        int kb_ = (TI) << 5;                                                    \
        uint32_t sA0_ = sb32 + (uint32_t)(ST) * 9728u;                          \
        uint32_t sB_  = sA0_ + 5120u;                                           \
        if (tid < 128) {                                                        \
            int r_ = tid >> 2, g4_ = tid & 3;                                   \
            cpa16(sA0_ + (uint32_t)(r_ * 80 + g4_ * 16),                        \
                  g_O + (size_t)(row0 + r_) * 2048 + ecol0 + kb_ + g4_ * 8);    \
        } else {                                                                \
            int t2 = tid - 128, r_ = t2 >> 2, g4_ = t2 & 3;                     \
            cpa16(sA0_ + 2560u + (uint32_t)(r_ * 80 + g4_ * 16),                \
                  g_O + (size_t)(640 + row0 + r_) * 2048 + ecol0 + kb_ + g4_ * 8); \
        }                                                                       \
        { int br_ = tid >> 4, g4_ = tid & 15;                                   \
          cpa16(sB_ + (uint32_t)(br_ * 288 + g4_ * 16),                         \
                Wz + (size_t)((TI) * 16 + br_) * 1024 + col0 + g4_ * 4); }      \
    } while (0)

    FU_ISSUE(0, 0); cpa_commit();
    FU_ISSUE(1, 1); cpa_commit();

    for (int ti = 0; ti < nt; ++ti) {
        cpa_wait<1>();
        __syncthreads();
        int tin = ti + 2;
        if (tin < nt) { FU_ISSUE(tin, tin % 3); }
        cpa_commit();

        const uint32_t* A0u = (const uint32_t*)(smb + (ti % 3) * 9728);
        const uint32_t* A1u = A0u + 640;
        const uint32_t* Bsu = (const uint32_t*)(smb + (ti % 3) * 9728 + 5120);
        #pragma unroll
        for (int s = 0; s < 2; ++s) {
            int rr = wm + g;
            uint32_t a0[4], a1[4];
            a0[0] = A0u[rr * 20 + s * 8 + j];       a0[1] = A0u[(rr + 8) * 20 + s * 8 + j];
            a0[2] = A0u[rr * 20 + s * 8 + 4 + j];   a0[3] = A0u[(rr + 8) * 20 + s * 8 + 4 + j];
            a1[0] = A1u[rr * 20 + s * 8 + j];       a1[1] = A1u[(rr + 8) * 20 + s * 8 + j];
            a1[2] = A1u[rr * 20 + s * 8 + 4 + j];   a1[3] = A1u[(rr + 8) * 20 + s * 8 + 4 + j];
            #pragma unroll
            for (int ni = 0; ni < 2; ++ni) {
                int nn = wn + ni * 8 + g;
                uint32_t b0 = Bsu[(s * 8 + j) * 72 + nn];
                uint32_t b1 = Bsu[(s * 8 + 4 + j) * 72 + nn];
                mma16(acc[0][ni], a0[0], a0[1], a0[2], a0[3], b0, b1);
                mma16(acc[1][ni], a1[0], a1[1], a1[2], a1[3], b0, b1);
            }
        }
    }
    #undef FU_ISSUE

    #pragma unroll
    for (int br = 0; br < 2; ++br) {
        float* Cf = g_FF + (size_t)(z * 2 + br) * 655360;
        #pragma unroll
        for (int ni = 0; ni < 2; ++ni) {
            int rr = row0 + wm + g, cc = col0 + wn + ni * 8 + 2 * j;
            *(float2*)(Cf + (size_t)rr * 1024 + cc) = make_float2(acc[br][ni][0], acc[br][ni][1]);
            *(float2*)(Cf + (size_t)(rr + 8) * 1024 + cc) = make_float2(acc[br][ni][2], acc[br][ni][3]);
        }
    }
}

// ---------- merge fuse halves + relu + residual -> d_out ----------
__global__ __launch_bounds__(256) void k_fmerge(
    const float* __restrict__ audio, const float* __restrict__ video,
    const float* __restrict__ bf, float* __restrict__ out)
{
    int i = blockIdx.x * 256 + threadIdx.x;   // float4 index over 163840
    float4 f00 = ((const float4*)g_FF)[i];                 // z0 br0
    float4 f01 = ((const float4*)(g_FF + 655360))[i];      // z0 br1
    float4 f10 = ((const float4*)(g_FF + 1310720))[i];     // z1 br0
    float4 f11 = ((const float4*)(g_FF + 1966080))[i];     // z1 br1
    float4 a = ((const float4*)audio)[i];
    float4 v = ((const float4*)video)[i];
    int cc = (i * 4) & 1023;
    float4 b = *(const float4*)(bf + cc);
    float4 o;
    o.x = a.x + v.x + fmaxf(f00.x + f10.x + b.x, 0.f) + fmaxf(f01.x + f11.x + b.x, 0.f);
    o.y = a.y + v.y + fmaxf(f00.y + f10.y + b.y, 0.f) + fmaxf(f01.y + f11.y + b.y, 0.f);
    o.z = a.z + v.z + fmaxf(f00.z + f10.z + b.z, 0.f) + fmaxf(f01.z + f11.z + b.z, 0.f);
    o.w = a.w + v.w + fmaxf(f00.w + f10.w + b.w, 0.f) + fmaxf(f01.w + f11.w + b.w, 0.f);
    ((float4*)out)[i] = o;
}

// ---------- fused co-attention branch, fp16: 2 e-tiles/warp, 3-stage ----------
// stage bytes: K[64][24]h = 3072, V[16][72]h = 2304 -> 5376/stage
__global__ __launch_bounds__(256, 2) void k_branch_tc()
{
    __shared__ char smb[3 * 5376];
    uint32_t sb32 = (uint32_t)__cvta_generic_to_shared(smb);

    int eblk = blockIdx.x, b = blockIdx.y, r = blockIdx.z;
    int tid = threadIdx.x, lane = tid & 31, warp = tid >> 5;
    int g = lane >> 2, j = lane & 3;

    const __half* gk  = g_K + (size_t)(r * 64 + b) * 16384;
    const __half* gvb = g_V + (size_t)r * 655360 + (size_t)b * 10240;

    uint32_t jf[2][4];
    {
        const __half* jb = g_J + (size_t)b * 20480;
        #pragma unroll
        for (int tile = 0; tile < 2; ++tile) {
            int eT = eblk * 256 + warp * 32 + tile * 16 + g;
            jf[tile][0] = hh2u(jb[(size_t)(2 * j) * 2048 + eT],
                               jb[(size_t)(2 * j + 1) * 2048 + eT]);
            jf[tile][1] = hh2u(jb[(size_t)(2 * j) * 2048 + eT + 8],
                               jb[(size_t)(2 * j + 1) * 2048 + eT + 8]);
            if (j == 0) {
                jf[tile][2] = hh2u(jb[(size_t)8 * 2048 + eT], jb[(size_t)9 * 2048 + eT]);
                jf[tile][3] = hh2u(jb[(size_t)8 * 2048 + eT + 8], jb[(size_t)9 * 2048 + eT + 8]);
            } else { jf[tile][2] = 0u; jf[tile][3] = 0u; }
        }
    }

    for (int i = tid; i < 3 * 6 * 36; i += 256) {
        int st = i / 216, rem = i - st * 216;
        int row = 10 + rem / 36, col = rem % 36;
        ((uint32_t*)(smb + st * 5376 + 3072))[row * 36 + col] = 0u;
    }

    #define BR_ISSUE(CH, ST) do {                                               \
        uint32_t base_ = sb32 + (uint32_t)(ST) * 5376u;                         \
        if (tid < 128) {                                                        \
            int d_ = tid >> 1, g4_ = tid & 1;                                   \
            cpa16(base_ + (uint32_t)(d_ * 48 + g4_ * 16),                       \
                  gk + (size_t)((CH) * 64 + d_) * 16 + g4_ * 8);                \
        } else if (tid < 208) {                                                 \
            int v_ = tid - 128, t_ = v_ >> 3, gi_ = v_ & 7;                     \
            cpa16(base_ + 3072u + (uint32_t)(t_ * 144 + gi_ * 16),              \
                  gvb + (size_t)t_ * 1024 + (CH) * 64 + gi_ * 8);               \
        }                                                                       \
    } while (0)

    BR_ISSUE(0, 0); cpa_commit();
    BR_ISSUE(1, 1); cpa_commit();

    float accW[2][2][4] = {};

    for (int ch = 0; ch < 16; ++ch) {
        cpa_wait<1>();
        __syncthreads();
        if (ch + 2 < 16) { BR_ISSUE(ch + 2, (ch + 2) % 3); }
        cpa_commit();

        const uint32_t* Ku = (const uint32_t*)(smb + (ch % 3) * 5376);
        const uint32_t* Vu = (const uint32_t*)(smb + (ch % 3) * 5376 + 3072);

        #pragma unroll
        for (int dh = 0; dh < 2; ++dh) {
            float accS[2][4][4] = {};
            #pragma unroll
            for (int ni = 0; ni < 4; ++ni) {
                int dd = dh * 32 + ni * 8 + g;
                uint32_t b0 = Ku[dd * 12 + j];
                uint32_t b1 = Ku[dd * 12 + 4 + j];
                mma16(accS[0][ni], jf[0][0], jf[0][1], jf[0][2], jf[0][3], b0, b1);
                mma16(accS[1][ni], jf[1][0], jf[1][1], jf[1][2], jf[1][3], b0, b1);
            }
            #pragma unroll
            for (int q = 0; q < 2; ++q) {
                uint32_t aa[2][4];
                #pragma unroll
                for (int et = 0; et < 2; ++et) {
                    aa[et][0] = tanh2(h2u(accS[et][2 * q][0],     accS[et][2 * q][1]));
                    aa[et][1] = tanh2(h2u(accS[et][2 * q][2],     accS[et][2 * q][3]));
                    aa[et][2] = tanh2(h2u(accS[et][2 * q + 1][0], accS[et][2 * q + 1][1]));
                    aa[et][3] = tanh2(h2u(accS[et][2 * q + 1][2], accS[et][2 * q + 1][3]));
                }
                #pragma unroll
                for (int nt = 0; nt < 2; ++nt) {
                    int tt = nt * 8 + g;
                    uint32_t b0 = Vu[tt * 36 + dh * 16 + q * 8 + j];
                    uint32_t b1 = Vu[tt * 36 + dh * 16 + q * 8 + 4 + j];
                    mma16(accW[0][nt], aa[0][0], aa[0][1], aa[0][2], aa[0][3], b0, b1);
                    mma16(accW[1][nt], aa[1][0], aa[1][1], aa[1][2], aa[1][3], b0, b1);
                }
            }
        }
    }
    #undef BR_ISSUE

    #pragma unroll
    for (int et = 0; et < 2; ++et) {
        int e = eblk * 256 + warp * 32 + et * 16 + g;
        #pragma unroll
        for (int nt = 0; nt < 2; ++nt) {
            int t0 = nt * 8 + 2 * j;
            if (t0 < 10) {
                size_t base = ((size_t)r * 640 + b * 10 + t0) * 2048;
                g_O[base + e]     = __float2half_rn(fmaxf(tanhx(accW[et][nt][0]), 0.0f));
                g_O[base + e + 8] = __float2half_rn(fmaxf(tanhx(accW[et][nt][2]), 0.0f));
            }
            if (t0 + 1 < 10) {
                size_t base = ((size_t)r * 640 + b * 10 + t0 + 1) * 2048;
                g_O[base + e]     = __float2half_rn(fmaxf(tanhx(accW[et][nt][1]), 0.0f));
                g_O[base + e + 8] = __float2half_rn(fmaxf(tanhx(accW[et][nt][3]), 0.0f));
            }
        }
    }
}

extern "C" void kernel_launch(void* const* d_in, const int* in_sizes, int n_in,
                              void* d_out, int out_size)
{
    const float* audio = (const float*)d_in[0];
    const float* video = (const float*)d_in[1];
    const float* Wq  = (const float*)d_in[2];
    const float* bq  = (const float*)d_in[3];
    const float* Wk1 = (const float*)d_in[4];
    const float* bk1 = (const float*)d_in[5];
    const float* Wk2 = (const float*)d_in[6];
    const float* bk2 = (const float*)d_in[7];
    const float* Wv1 = (const float*)d_in[8];
    const float* bv1 = (const float*)d_in[9];
    const float* Wv2 = (const float*)d_in[10];
    const float* bv2 = (const float*)d_in[11];
    const float* Wf  = (const float*)d_in[12];
    const float* bf  = (const float*)d_in[13];
    float* out = (float*)d_out;

    static __half* wb = nullptr;
    static cudaStream_t s1 = nullptr, s2 = nullptr;
    static cudaEvent_t eS, eR, eK, eV;
    if (!wb) {
        cudaGetSymbolAddress((void**)&wb, g_W);
        cudaStreamCreateWithFlags(&s1, cudaStreamNonBlocking);
        cudaStreamCreateWithFlags(&s2, cudaStreamNonBlocking);
        cudaEventCreateWithFlags(&eS, cudaEventDisableTiming);
        cudaEventCreateWithFlags(&eR, cudaEventDisableTiming);
        cudaEventCreateWithFlags(&eK, cudaEventDisableTiming);
        cudaEventCreateWithFlags(&eV, cudaEventDisableTiming);
    }
    const __half* hA = wb + OW_A;
    const __half* hV = wb + OW_V;
    const uint32_t* Wqu  = (const uint32_t*)(wb + OW_WQ);
    const uint32_t* Wv1u = (const uint32_t*)(wb + OW_WV1);
    const uint32_t* Wv2u = (const uint32_t*)(wb + OW_WV2);
    const uint32_t* Wfu  = (const uint32_t*)(wb + OW_WF);

    // fork: key linears on s2 (raw fp32 inputs)
    cudaEventRecord(eS, 0);
    cudaStreamWaitEvent(s2, eS, 0);
    k_key<<<dim3(64, 2), 256, 0, s2>>>(audio, video, Wk1, bk1, Wk2, bk2);
    cudaEventRecord(eK, s2);

    // fp16 conversion
    k_round<<<4736, 256>>>(audio, video, Wq, Wv1, Wv2, Wf);
    cudaEventRecord(eR, 0);

    // val1/val2 on s1 (z selects branch), concurrent with joint
    cudaStreamWaitEvent(s1, eR, 0);
    k_gemm_tc<<<dim3(16, 10, 2), 256, 29184, s1>>>(
        hA, hA, hV, hV, 1024, 1024, Wv1u, Wv2u, bv1, bv2,
        1, (size_t)640 * 1024, 1024, 1024, 0);
    cudaEventRecord(eV, s1);

    // joint split-K: z = khalf.  khalf0: audio x Wq[0:1024); khalf1: video x Wq[1024:2048)
    k_gemm_tc<<<dim3(32, 10, 2), 256, 29184>>>(
        hA, hA, hV, hV, 2048, 1024, Wqu, Wqu + (size_t)512 * 2048, nullptr, nullptr,
        2, (size_t)1310720, 2048, 1024, 1);
    // merge joint halves -> g_J fp16
    k_jmerge<<<1280, 256>>>(bq);

    // join, then branch
    cudaStreamWaitEvent(0, eV, 0);
    cudaStreamWaitEvent(0, eK, 0);
    k_branch_tc<<<dim3(8, 64, 2), 256>>>();

    // fuse split-K (z = khalf over e), then merge + relu + residual -> d_out
    k_fuse<<<dim3(16, 20, 2), 256, 29184>>>(Wfu);
    k_fmerge<<<640, 256>>>(audio, video, bf, out);
}